// round 9
// baseline (speedup 1.0000x reference)
#include <cuda_runtime.h>
#include <cuda_bf16.h>
#include <math.h>

// ---------------- problem constants ----------------
#define NMAX 50000
#define EMAX 800000
#define D 128
#define NH 4
#define HC 32

// ---------------- scratch pool (lifetime-carved) ----------------
// slot size S = NMAX*128
//  [0,S)      h_mod            (later reused as y1 = aggr@Wp)
//  [S,2S)     xl               (live through edge pass C)
//  [2S,3S)    xe               (later reused as z = LayerNorm(y1))
//  [3S,4S)    gA = xl+xe       (dead after pass A; reused as z2 lower half)
//  [4S,5S)    gB = xr-xe       (dead after pass A; reused as z2 upper half)
//  [5S, +4E)  logit / ex
//  then aggr (S), denom (4N), amax enc (4N), misc (style 256, bpp 128, zeros)
#define SLOT ((size_t)NMAX * 128)
#define OFF_HMOD   ((size_t)0)
#define OFF_XL     (SLOT)
#define OFF_XE     (2 * SLOT)
#define OFF_GA     (3 * SLOT)
#define OFF_GB     (4 * SLOT)
#define OFF_LOGIT  (5 * SLOT)
#define OFF_AGGR   (OFF_LOGIT + (size_t)EMAX * 4)
#define OFF_DENOM  (OFF_AGGR + SLOT)
#define OFF_AMAX   (OFF_DENOM + (size_t)NMAX * 4)
#define OFF_MISC   (OFF_AMAX + (size_t)NMAX * 4)
#define POOL_TOTAL (OFF_MISC + 1024)

__device__ __align__(16) float g_pool[POOL_TOTAL];

// ---------------- helpers ----------------
__device__ __forceinline__ unsigned enc_float(float f) {
    unsigned u = __float_as_uint(f);
    return (u & 0x80000000u) ? ~u : (u | 0x80000000u);
}
__device__ __forceinline__ float dec_float(unsigned u) {
    return (u & 0x80000000u) ? __uint_as_float(u ^ 0x80000000u)
                             : __uint_as_float(~u);
}
__device__ __forceinline__ float gelu_exact(float x) {
    return 0.5f * x * (1.0f + erff(x * 0.70710678118654752f));
}

// ---------------- zero accumulators ----------------
__global__ void zero_k(unsigned* __restrict__ amax, float* __restrict__ denom,
                       float* __restrict__ aggr, int n) {
    int i = blockIdx.x * blockDim.x + threadIdx.x;
    int stride = gridDim.x * blockDim.x;
    int n4 = n * 4;
    for (int j = i; j < n4; j += stride) { amax[j] = 0u; denom[j] = 0.0f; }
    int n128 = n * 128;
    for (int j = i; j < n128; j += stride) aggr[j] = 0.0f;
}

// ---------------- tiny precompute: style = t_emb@fc_W+fc_b ; bpp = gat_b@Wp+bp
__global__ void prep_k(const float* __restrict__ t_emb, const float* __restrict__ fc_W,
                       const float* __restrict__ fc_b, const float* __restrict__ gat_b,
                       const float* __restrict__ Wp, const float* __restrict__ bp,
                       float* __restrict__ style, float* __restrict__ bpp) {
    int j = threadIdx.x;  // 384 threads
    if (j < 256) {
        float s = fc_b[j];
        #pragma unroll 4
        for (int k = 0; k < 128; k++) s += t_emb[k] * fc_W[k * 256 + j];
        style[j] = s;
    } else {
        int c = j - 256;
        float s = bp[c];
        #pragma unroll 4
        for (int k = 0; k < 128; k++) s += gat_b[k] * Wp[k * 128 + c];
        bpp[c] = s;
    }
}

// ---------------- AdaGN: GroupNorm(G=8) + style modulation ----------------
__global__ void adagn_k(const float* __restrict__ hs, const float* __restrict__ gn_w,
                        const float* __restrict__ gn_b, const float* __restrict__ style,
                        float* __restrict__ hmod, int n) {
    int node = blockIdx.x;
    int t = threadIdx.x;  // 128 threads = 128 channels
    float x = hs[(size_t)node * 128 + t];
    float s = x, s2 = x * x;
    #pragma unroll
    for (int w = 8; w >= 1; w >>= 1) {  // reduce within 16-lane groups
        s  += __shfl_xor_sync(0xffffffffu, s, w);
        s2 += __shfl_xor_sync(0xffffffffu, s2, w);
    }
    float mu  = s * (1.0f / 16.0f);
    float var = s2 * (1.0f / 16.0f) - mu * mu;
    float nx  = (x - mu) * rsqrtf(var + 1e-5f);
    float g = style[t], b = style[128 + t];
    hmod[(size_t)node * 128 + t] = (nx * gn_w[t] + gn_b[t]) * (1.0f + g) + b;
}

// ---------------- SGEMM: C(MxN) = A(MxK) @ B(KxN) + bias, with epilogue ----
// EPI 0: +bias ;  EPI 1: gelu(+bias) ;  EPI 2: +bias + R (residual)
template <int EPI>
__global__ __launch_bounds__(256)
void sgemm_k(const float* __restrict__ A, int K, const float* __restrict__ B,
             const float* __restrict__ bias, const float* __restrict__ R,
             float* __restrict__ C, int M, int Nout) {
    __shared__ float As[16][128];
    __shared__ float Bs[16][128];
    int t = threadIdx.x;
    int m0 = blockIdx.x * 128;
    int n0 = blockIdx.y * 128;
    int ty = t >> 4, tx = t & 15;
    float acc[8][8];
    #pragma unroll
    for (int i = 0; i < 8; i++)
        #pragma unroll
        for (int j = 0; j < 8; j++) acc[i][j] = 0.0f;

    for (int k0 = 0; k0 < K; k0 += 16) {
        #pragma unroll
        for (int r = 0; r < 2; r++) {
            int idx = t + r * 256;
            int ar = idx >> 2;
            int ac = (idx & 3) * 4;
            float4 v = make_float4(0.f, 0.f, 0.f, 0.f);
            int gr = m0 + ar;
            if (gr < M) v = *(const float4*)(A + (size_t)gr * K + k0 + ac);
            As[ac + 0][ar] = v.x; As[ac + 1][ar] = v.y;
            As[ac + 2][ar] = v.z; As[ac + 3][ar] = v.w;
        }
        #pragma unroll
        for (int r = 0; r < 2; r++) {
            int idx = t + r * 256;
            int brr = idx >> 5;
            int bc = (idx & 31) * 4;
            float4 v = *(const float4*)(B + (size_t)(k0 + brr) * Nout + n0 + bc);
            *(float4*)&Bs[brr][bc] = v;
        }
        __syncthreads();
        #pragma unroll
        for (int kk = 0; kk < 16; kk++) {
            float a[8], b[8];
            *(float4*)&a[0] = *(const float4*)&As[kk][ty * 8];
            *(float4*)&a[4] = *(const float4*)&As[kk][ty * 8 + 4];
            *(float4*)&b[0] = *(const float4*)&Bs[kk][tx * 8];
            *(float4*)&b[4] = *(const float4*)&Bs[kk][tx * 8 + 4];
            #pragma unroll
            for (int i = 0; i < 8; i++)
                #pragma unroll
                for (int j = 0; j < 8; j++) acc[i][j] += a[i] * b[j];
        }
        __syncthreads();
    }

    #pragma unroll
    for (int i = 0; i < 8; i++) {
        int gr = m0 + ty * 8 + i;
        if (gr >= M) break;
        #pragma unroll
        for (int j = 0; j < 8; j += 4) {
            int gc = n0 + tx * 8 + j;
            float o[4];
            #pragma unroll
            for (int q = 0; q < 4; q++) {
                float v = acc[i][j + q] + bias[gc + q];
                if (EPI == 1) v = gelu_exact(v);
                if (EPI == 2) v += R[(size_t)gr * Nout + gc + q];
                o[q] = v;
            }
            *(float4*)(C + (size_t)gr * Nout + gc) =
                make_float4(o[0], o[1], o[2], o[3]);
        }
    }
}

// ---------------- combine: gA = xl + xe ; gB = gB - xe (gB held xr) -------
__global__ void combine_k(const float* __restrict__ xl, const float* __restrict__ xe,
                          float* __restrict__ gA, float* __restrict__ gB, int n128_4) {
    int i = blockIdx.x * blockDim.x + threadIdx.x;
    int stride = gridDim.x * blockDim.x;
    const float4* xl4 = (const float4*)xl;
    const float4* xe4 = (const float4*)xe;
    float4* gA4 = (float4*)gA;
    float4* gB4 = (float4*)gB;
    for (int j = i; j < n128_4; j += stride) {
        float4 l = xl4[j], e = xe4[j], r = gB4[j];
        gA4[j] = make_float4(l.x + e.x, l.y + e.y, l.z + e.z, l.w + e.w);
        gB4[j] = make_float4(r.x - e.x, r.y - e.y, r.z - e.z, r.w - e.w);
    }
}

// ---------------- edge pass A: logits + segment max (warp/edge) -----------
__global__ void edge_logits_k(const int* __restrict__ ei, const float* __restrict__ pos,
                              const float* __restrict__ gA, const float* __restrict__ gB,
                              const float* __restrict__ We, const float* __restrict__ att,
                              float* __restrict__ logit, unsigned* __restrict__ amax, int E) {
    __shared__ float sW0[128], sW1[128], sAtt[128];
    int t = threadIdx.x;
    if (t < 128) {
        sW0[t]  = We[128 * 128 + t];
        sW1[t]  = We[129 * 128 + t];
        sAtt[t] = att[t];
    }
    __syncthreads();
    int e = (blockIdx.x * blockDim.x + t) >> 5;
    if (e >= E) return;
    int l = t & 31;
    int s = ei[e], d = ei[E + e];
    float2 ps = *(const float2*)(pos + 2 * (size_t)s);
    float2 pd = *(const float2*)(pos + 2 * (size_t)d);
    float rx = ps.x - pd.x, ry = ps.y - pd.y;
    float inv = 1.0f / (rx * rx + ry * ry + 1e-8f);
    float ox = -ry * inv, oy = rx * inv;
    const float* as = gA + (size_t)s * 128;
    const float* bd = gB + (size_t)d * 128;
    float p[4];
    #pragma unroll
    for (int k = 0; k < 4; k++) {
        int ch = k * 32 + l;
        float v = as[ch] + bd[ch] + ox * sW0[ch] + oy * sW1[ch];
        v = v > 0.0f ? v : 0.2f * v;          // leaky_relu(0.2)
        p[k] = v * sAtt[ch];
    }
    #pragma unroll
    for (int w = 16; w >= 1; w >>= 1) {
        #pragma unroll
        for (int k = 0; k < 4; k++) p[k] += __shfl_xor_sync(0xffffffffu, p[k], w);
    }
    if (l == 0)
        *(float4*)(logit + (size_t)e * 4) = make_float4(p[0], p[1], p[2], p[3]);
    if (l < 4)
        atomicMax(&amax[(size_t)d * 4 + l], enc_float(p[l]));
}

// ---------------- edge pass B: ex = exp(logit - max), denom += ex ---------
__global__ void edge_exp_k(const int* __restrict__ ei, float* __restrict__ lg,
                           const unsigned* __restrict__ amax, float* __restrict__ denom, int E) {
    int e = blockIdx.x * blockDim.x + threadIdx.x;
    if (e >= E) return;
    int d = ei[E + e];
    float4 v = *(float4*)(lg + (size_t)e * 4);
    float r[4] = {v.x, v.y, v.z, v.w};
    #pragma unroll
    for (int k = 0; k < 4; k++) {
        float am = dec_float(amax[(size_t)d * 4 + k]);
        float ex = expf(r[k] - am);
        r[k] = ex;
        atomicAdd(&denom[(size_t)d * 4 + k], ex);
    }
    *(float4*)(lg + (size_t)e * 4) = make_float4(r[0], r[1], r[2], r[3]);
}

// ---------------- edge pass C: aggr[dst] += alpha * xl[src] (warp/edge) ---
__global__ void edge_aggr_k(const int* __restrict__ ei, const float* __restrict__ lg,
                            const float* __restrict__ denom, const float* __restrict__ xl,
                            float* __restrict__ aggr, int E) {
    int t = threadIdx.x;
    int e = (blockIdx.x * blockDim.x + t) >> 5;
    if (e >= E) return;
    int l = t & 31;
    int s = ei[e], d = ei[E + e];
    float4 ex = *(const float4*)(lg + (size_t)e * 4);
    float al[4];
    al[0] = ex.x / (denom[(size_t)d * 4 + 0] + 1e-16f);
    al[1] = ex.y / (denom[(size_t)d * 4 + 1] + 1e-16f);
    al[2] = ex.z / (denom[(size_t)d * 4 + 2] + 1e-16f);
    al[3] = ex.w / (denom[(size_t)d * 4 + 3] + 1e-16f);
    const float* xs = xl + (size_t)s * 128;
    float* od = aggr + (size_t)d * 128;
    #pragma unroll
    for (int k = 0; k < 4; k++) {
        int ch = k * 32 + l;
        atomicAdd(&od[ch], al[k] * xs[ch]);
    }
}

// ---------------- LayerNorm over D=128 ----------------
__global__ void ln_k(const float* __restrict__ y, const float* __restrict__ w,
                     const float* __restrict__ b, float* __restrict__ z, int n) {
    int node = blockIdx.x;
    int t = threadIdx.x;  // 128
    float x = y[(size_t)node * 128 + t];
    float s = x, s2 = x * x;
    #pragma unroll
    for (int wdt = 16; wdt >= 1; wdt >>= 1) {
        s  += __shfl_xor_sync(0xffffffffu, s, wdt);
        s2 += __shfl_xor_sync(0xffffffffu, s2, wdt);
    }
    __shared__ float ss[4], ss2[4];
    int wid = t >> 5;
    if ((t & 31) == 0) { ss[wid] = s; ss2[wid] = s2; }
    __syncthreads();
    s  = ss[0] + ss[1] + ss[2] + ss[3];
    s2 = ss2[0] + ss2[1] + ss2[2] + ss2[3];
    float mu  = s * (1.0f / 128.0f);
    float var = s2 * (1.0f / 128.0f) - mu * mu;
    z[(size_t)node * 128 + t] = (x - mu) * rsqrtf(var + 1e-5f) * w[t] + b[t];
}

// ---------------- launch ----------------
extern "C" void kernel_launch(void* const* d_in, const int* in_sizes, int n_in,
                              void* d_out, int out_size) {
    const float* h_target = (const float*)d_in[0];
    const float* h_source = (const float*)d_in[1];
    const int*   ei       = (const int*)d_in[2];   // int32! (JAX x64 disabled)
    const float* pos      = (const float*)d_in[3];
    const float* t_emb    = (const float*)d_in[4];
    const float* gn_w     = (const float*)d_in[5];
    const float* gn_b     = (const float*)d_in[6];
    const float* fc_W     = (const float*)d_in[7];
    const float* fc_b     = (const float*)d_in[8];
    const float* Wl       = (const float*)d_in[9];
    const float* bl       = (const float*)d_in[10];
    const float* Wr       = (const float*)d_in[11];
    const float* br       = (const float*)d_in[12];
    const float* We       = (const float*)d_in[13];
    const float* att      = (const float*)d_in[14];
    const float* gat_b    = (const float*)d_in[15];
    const float* Wp       = (const float*)d_in[16];
    const float* bp       = (const float*)d_in[17];
    const float* ln_w     = (const float*)d_in[18];
    const float* ln_b     = (const float*)d_in[19];
    const float* W1       = (const float*)d_in[20];
    const float* b1       = (const float*)d_in[21];
    const float* W2       = (const float*)d_in[22];
    const float* b2       = (const float*)d_in[23];

    int n = in_sizes[0] / 128;
    int e = in_sizes[2] / 2;

    float* pool = nullptr;
    cudaGetSymbolAddress((void**)&pool, g_pool);
    float*    g_hmod  = pool + OFF_HMOD;   // later y1
    float*    g_xl    = pool + OFF_XL;
    float*    g_xe    = pool + OFF_XE;     // later z
    float*    g_gA    = pool + OFF_GA;     // later z2 (spans gA+gB)
    float*    g_gB    = pool + OFF_GB;
    float*    g_logit = pool + OFF_LOGIT;
    float*    g_aggr  = pool + OFF_AGGR;
    float*    g_denom = pool + OFF_DENOM;
    unsigned* g_amax  = (unsigned*)(pool + OFF_AMAX);
    float*    g_style = pool + OFF_MISC;
    float*    g_bpp   = pool + OFF_MISC + 256;
    float*    g_zeros = pool + OFF_MISC + 384;  // never written: stays 0
    float*    g_y1    = g_hmod;
    float*    g_z     = g_xe;
    float*    g_z2    = g_gA;

    int mblocks = (n + 127) / 128;

    // 0) reset accumulators for this replay
    zero_k<<<512, 256>>>(g_amax, g_denom, g_aggr, n);
    // 1) tiny precompute
    prep_k<<<1, 384>>>(t_emb, fc_W, fc_b, gat_b, Wp, bp, g_style, g_bpp);
    // 2) AdaGN
    adagn_k<<<n, 128>>>(h_source, gn_w, gn_b, g_style, g_hmod, n);
    // 3) node GEMMs: xl = hmod@Wl+bl ; xr(into gB) = hmod@Wr+br ; xe = hmod@We_phys
    sgemm_k<0><<<dim3(mblocks, 1), 256>>>(g_hmod, 128, Wl, bl, nullptr, g_xl, n, 128);
    sgemm_k<0><<<dim3(mblocks, 1), 256>>>(g_hmod, 128, Wr, br, nullptr, g_gB, n, 128);
    sgemm_k<0><<<dim3(mblocks, 1), 256>>>(g_hmod, 128, We, g_zeros, nullptr, g_xe, n, 128);
    // 4) combine: gA = xl+xe ; gB = xr-xe
    combine_k<<<512, 256>>>(g_xl, g_xe, g_gA, g_gB, n * 32);
    // 5) edge passes
    int eblocks = (e + 7) / 8;
    edge_logits_k<<<eblocks, 256>>>(ei, pos, g_gA, g_gB, We, att, g_logit, g_amax, e);
    edge_exp_k<<<(e + 255) / 256, 256>>>(ei, g_logit, g_amax, g_denom, e);
    edge_aggr_k<<<eblocks, 256>>>(ei, g_logit, g_denom, g_xl, g_aggr, e);
    // 6) post-GAT: y1 = aggr@Wp + (gat_b@Wp + bp)
    sgemm_k<0><<<dim3(mblocks, 1), 256>>>(g_aggr, 128, Wp, g_bpp, nullptr, g_y1, n, 128);
    // 7) LayerNorm
    ln_k<<<n, 128>>>(g_y1, ln_w, ln_b, g_z, n);
    // 8) z2 = gelu(z@W1 + b1)
    sgemm_k<1><<<dim3(mblocks, 2), 256>>>(g_z, 128, W1, b1, nullptr, g_z2, n, 256);
    // 9) out = z2@W2 + b2 + h_target
    sgemm_k<2><<<dim3(mblocks, 1), 256>>>(g_z2, 256, W2, b2, h_target, (float*)d_out, n, 128);
}